// round 2
// baseline (speedup 1.0000x reference)
#include <cuda_runtime.h>
#include <cuda_bf16.h>

// ---------------------------------------------------------------------------
// GPUManifoldFeatureEncoder: edge-feature MLP + BN + scatter-mean + proj + BN
//
// Key fold: edge BN is per-feature affine h*s+t, so
//   scatter_add(bn(h)) = s*scatter_add(h) + t*degree
// => single pass over edges (no h materialization, no recompute).
//
// edge_index is int32 on the device side (harness converts int64 -> int32).
// ---------------------------------------------------------------------------

#define MAX_N 131072

__device__ float  g_node_acc[MAX_N * 16];   // scatter accumulator (raw h)
__device__ float  g_degree[MAX_N];
__device__ double g_esum[16], g_esq[16];    // edge BN stats
__device__ double g_nsum[16], g_nsq[16];    // node BN stats
__device__ float  g_es[16], g_et[16];       // edge BN scale/shift
__device__ float  g_ns[16], g_nt[16];       // node BN scale/shift

__device__ __forceinline__ float gelu_exact(float x) {
    return 0.5f * x * (1.0f + erff(x * 0.70710678118654752440f));
}

// ---------------------------------------------------------------------------
__global__ void k_zero(int N) {
    int i = blockIdx.x * blockDim.x + threadIdx.x;
    int tot = N * 16;
    if (i < tot) g_node_acc[i] = 0.0f;
    if (i < N)   g_degree[i]   = 0.0f;
    if (i < 16) {
        g_esum[i] = 0.0; g_esq[i] = 0.0;
        g_nsum[i] = 0.0; g_nsq[i] = 0.0;
    }
}

// ---------------------------------------------------------------------------
// Edge kernel: gather geometry, 8->64->32->16 MLP (exact GELU), accumulate
// BN stats in registers, scatter h via float4 atomics.
// ---------------------------------------------------------------------------
__global__ __launch_bounds__(128)
void k_edge(const float* __restrict__ coords,
            const float* __restrict__ normals,
            const float* __restrict__ curv,
            const int* __restrict__ row,
            const int* __restrict__ col,
            const float* __restrict__ W1, const float* __restrict__ b1,
            const float* __restrict__ W2, const float* __restrict__ b2,
            const float* __restrict__ W3, const float* __restrict__ b3,
            int E, int N)
{
    __shared__ float sW1[8 * 64];
    __shared__ float sW2[64 * 32];
    __shared__ float sW3[32 * 16];
    __shared__ float sb1[64], sb2[32], sb3[16];
    __shared__ float redS[4][16], redQ[4][16];

    for (int i = threadIdx.x; i < 512;  i += 128) sW1[i] = W1[i];
    for (int i = threadIdx.x; i < 2048; i += 128) sW2[i] = W2[i];
    for (int i = threadIdx.x; i < 512;  i += 128) sW3[i] = W3[i];
    if (threadIdx.x < 64) sb1[threadIdx.x] = b1[threadIdx.x];
    if (threadIdx.x < 32) sb2[threadIdx.x] = b2[threadIdx.x];
    if (threadIdx.x < 16) sb3[threadIdx.x] = b3[threadIdx.x];
    __syncthreads();

    float lsum[16], lsq[16];
#pragma unroll
    for (int k = 0; k < 16; k++) { lsum[k] = 0.0f; lsq[k] = 0.0f; }

    const int stride = gridDim.x * blockDim.x;
    for (int e = blockIdx.x * blockDim.x + threadIdx.x; e < E; e += stride) {
        const int r = row[e];
        const int c = col[e];
        // safety guard: if index model is ever wrong, report wrong-answer
        // (diagnosable) instead of crashing
        if ((unsigned)r >= (unsigned)N || (unsigned)c >= (unsigned)N) continue;

        const float prx = coords[3*r+0], pry = coords[3*r+1], prz = coords[3*r+2];
        const float pcx = coords[3*c+0], pcy = coords[3*c+1], pcz = coords[3*c+2];
        const float dx = pcx - prx, dy = pcy - pry, dz = pcz - prz;

        const float nrx = normals[3*r+0], nry = normals[3*r+1], nrz = normals[3*r+2];
        const float ncx = normals[3*c+0], ncy = normals[3*c+1], ncz = normals[3*c+2];

        const float ndot = nrx*ncx + nry*ncy + nrz*ncz;
        const float d2   = dx*dx + dy*dy + dz*dz;
        const float dn   = sqrtf(d2) + 1e-8f;
        const float inv  = 1.0f / dn;
        float cr = (nrx*dx + nry*dy + nrz*dz) * inv;
        float cc = (ncx*dx + ncy*dy + ncz*dz) * inv;
        // clip(-1+1e-8, 1-1e-8) rounds to [-1, 1] in fp32 (same as jax f32)
        cr = fminf(1.0f, fmaxf(-1.0f, cr));
        cc = fminf(1.0f, fmaxf(-1.0f, cc));

        float ef[8];
        ef[0] = dx; ef[1] = dy; ef[2] = dz;
        ef[3] = ndot; ef[4] = cr; ef[5] = cc;
        ef[6] = curv[4*c+0] - curv[4*r+0];
        ef[7] = curv[4*c+1] - curv[4*r+1];

        // Layer 2 accumulator; stream layer-1 outputs one at a time
        float acc2[32];
#pragma unroll
        for (int j = 0; j < 32; j++) acc2[j] = sb2[j];

#pragma unroll
        for (int i = 0; i < 64; i++) {
            float a = sb1[i];
#pragma unroll
            for (int k = 0; k < 8; k++) a = fmaf(ef[k], sW1[k*64 + i], a);
            const float x = gelu_exact(a);
#pragma unroll
            for (int j = 0; j < 32; j++) acc2[j] = fmaf(x, sW2[i*32 + j], acc2[j]);
        }

        float h[16];
#pragma unroll
        for (int k = 0; k < 16; k++) h[k] = sb3[k];
#pragma unroll
        for (int j = 0; j < 32; j++) {
            const float x = gelu_exact(acc2[j]);
#pragma unroll
            for (int k = 0; k < 16; k++) h[k] = fmaf(x, sW3[j*16 + k], h[k]);
        }

        // BN stats (local accumulation, amortized reduction at end)
#pragma unroll
        for (int k = 0; k < 16; k++) {
            lsum[k] += h[k];
            lsq[k]   = fmaf(h[k], h[k], lsq[k]);
        }

        // scatter h to both endpoints (HW float4 red on sm_90+)
        float4* ar = reinterpret_cast<float4*>(&g_node_acc[(size_t)r * 16]);
        float4* ac = reinterpret_cast<float4*>(&g_node_acc[(size_t)c * 16]);
#pragma unroll
        for (int q = 0; q < 4; q++) {
            float4 v = make_float4(h[4*q+0], h[4*q+1], h[4*q+2], h[4*q+3]);
            atomicAdd(ar + q, v);
            atomicAdd(ac + q, v);
        }
        atomicAdd(&g_degree[r], 1.0f);
        atomicAdd(&g_degree[c], 1.0f);
    }

    // warp reduce 32 quantities, then cross-warp via shared, one atomic per feat
#pragma unroll
    for (int k = 0; k < 16; k++) {
        float s = lsum[k], q = lsq[k];
#pragma unroll
        for (int o = 16; o > 0; o >>= 1) {
            s += __shfl_xor_sync(0xffffffffu, s, o);
            q += __shfl_xor_sync(0xffffffffu, q, o);
        }
        if ((threadIdx.x & 31) == 0) {
            redS[threadIdx.x >> 5][k] = s;
            redQ[threadIdx.x >> 5][k] = q;
        }
    }
    __syncthreads();
    if (threadIdx.x < 16) {
        double s = 0.0, q = 0.0;
#pragma unroll
        for (int w = 0; w < 4; w++) { s += (double)redS[w][threadIdx.x];
                                      q += (double)redQ[w][threadIdx.x]; }
        atomicAdd(&g_esum[threadIdx.x], s);
        atomicAdd(&g_esq[threadIdx.x],  q);
    }
}

// ---------------------------------------------------------------------------
__global__ void k_ecoef(const float* __restrict__ g, const float* __restrict__ b,
                        int E)
{
    int j = threadIdx.x;
    if (j < 16) {
        double invE = 1.0 / (double)E;
        double m = g_esum[j] * invE;
        double v = g_esq[j] * invE - m * m;
        double s = (double)g[j] / sqrt(v + 1e-5);
        g_es[j] = (float)s;
        g_et[j] = (float)((double)b[j] - m * s);
    }
}

// ---------------------------------------------------------------------------
// Node kernel: fold edge-BN affine, mean-by-degree, 16x16 projection, write
// pre-BN output and accumulate node-BN stats.
// ---------------------------------------------------------------------------
__global__ __launch_bounds__(256)
void k_node(const float* __restrict__ Wp, const float* __restrict__ bp,
            int N, float* __restrict__ out)
{
    __shared__ float sWp[256], sbp[16], ses[16], set_[16];
    __shared__ float redS[8][16], redQ[8][16];
    if (threadIdx.x < 256) sWp[threadIdx.x] = Wp[threadIdx.x];
    if (threadIdx.x < 16) {
        sbp[threadIdx.x]  = bp[threadIdx.x];
        ses[threadIdx.x]  = g_es[threadIdx.x];
        set_[threadIdx.x] = g_et[threadIdx.x];
    }
    __syncthreads();

    float lsum[16], lsq[16];
#pragma unroll
    for (int k = 0; k < 16; k++) { lsum[k] = 0.0f; lsq[k] = 0.0f; }

    const int n = blockIdx.x * blockDim.x + threadIdx.x;
    if (n < N) {
        const float deg  = g_degree[n];
        const float invd = 1.0f / fmaxf(deg, 1.0f);
        float pre[16];
#pragma unroll
        for (int j = 0; j < 16; j++) {
            const float a = g_node_acc[n * 16 + j];
            pre[j] = (ses[j] * a + set_[j] * deg) * invd;
        }
        float y[16];
#pragma unroll
        for (int k = 0; k < 16; k++) y[k] = sbp[k];
#pragma unroll
        for (int j = 0; j < 16; j++)
#pragma unroll
            for (int k = 0; k < 16; k++) y[k] = fmaf(pre[j], sWp[j*16 + k], y[k]);
#pragma unroll
        for (int k = 0; k < 16; k++) {
            out[n * 16 + k] = y[k];
            lsum[k] = y[k];
            lsq[k]  = y[k] * y[k];
        }
    }

#pragma unroll
    for (int k = 0; k < 16; k++) {
        float s = lsum[k], q = lsq[k];
#pragma unroll
        for (int o = 16; o > 0; o >>= 1) {
            s += __shfl_xor_sync(0xffffffffu, s, o);
            q += __shfl_xor_sync(0xffffffffu, q, o);
        }
        if ((threadIdx.x & 31) == 0) {
            redS[threadIdx.x >> 5][k] = s;
            redQ[threadIdx.x >> 5][k] = q;
        }
    }
    __syncthreads();
    if (threadIdx.x < 16) {
        double s = 0.0, q = 0.0;
#pragma unroll
        for (int w = 0; w < 8; w++) { s += (double)redS[w][threadIdx.x];
                                      q += (double)redQ[w][threadIdx.x]; }
        atomicAdd(&g_nsum[threadIdx.x], s);
        atomicAdd(&g_nsq[threadIdx.x],  q);
    }
}

// ---------------------------------------------------------------------------
__global__ void k_ncoef(const float* __restrict__ g, const float* __restrict__ b,
                        int N)
{
    int j = threadIdx.x;
    if (j < 16) {
        double invN = 1.0 / (double)N;
        double m = g_nsum[j] * invN;
        double v = g_nsq[j] * invN - m * m;
        double s = (double)g[j] / sqrt(v + 1e-5);
        g_ns[j] = (float)s;
        g_nt[j] = (float)((double)b[j] - m * s);
    }
}

// ---------------------------------------------------------------------------
__global__ void k_norm(float* __restrict__ out, int total)
{
    int i = blockIdx.x * blockDim.x + threadIdx.x;
    if (i < total) {
        int j = i & 15;
        out[i] = fmaf(out[i], g_ns[j], g_nt[j]);
    }
}

// ---------------------------------------------------------------------------
extern "C" void kernel_launch(void* const* d_in, const int* in_sizes, int n_in,
                              void* d_out, int out_size)
{
    const float* coords  = (const float*)d_in[0];
    const float* normals = (const float*)d_in[1];
    const float* curv    = (const float*)d_in[2];
    const int*   ei      = (const int*)d_in[3];   // int64 ref -> int32 on device
    const float* W1 = (const float*)d_in[4];
    const float* b1 = (const float*)d_in[5];
    const float* W2 = (const float*)d_in[6];
    const float* b2 = (const float*)d_in[7];
    const float* W3 = (const float*)d_in[8];
    const float* b3 = (const float*)d_in[9];
    const float* Wp = (const float*)d_in[10];
    const float* bp = (const float*)d_in[11];
    const float* beg = (const float*)d_in[12];
    const float* beb = (const float*)d_in[13];
    const float* bng = (const float*)d_in[14];
    const float* bnb = (const float*)d_in[15];

    const int N = in_sizes[0] / 3;
    const int E = in_sizes[3] / 2;
    const int* row = ei;
    const int* col = ei + E;
    float* out = (float*)d_out;

    k_zero<<<(N * 16 + 255) / 256, 256>>>(N);
    k_edge<<<2368, 128>>>(coords, normals, curv, row, col,
                          W1, b1, W2, b2, W3, b3, E, N);
    k_ecoef<<<1, 32>>>(beg, beb, E);
    k_node<<<(N + 255) / 256, 256>>>(Wp, bp, N, out);
    k_ncoef<<<1, 32>>>(bng, bnb, N);
    k_norm<<<(N * 16 + 255) / 256, 256>>>(out, N * 16);
}

// round 3
// speedup vs baseline: 1.0082x; 1.0082x over previous
#include <cuda_runtime.h>
#include <cuda_bf16.h>

// ---------------------------------------------------------------------------
// GPUManifoldFeatureEncoder — round 2 optimization:
//  * 2 edges per thread, all MLP math in packed fma.rn.f32x2 (Blackwell FFMA2)
//  * weights duplicated (w,w) in shared -> packed multiplier via 1 LDS.64
//  * exact-GELU replaced by shared-mem lerp LUT (abs err ~8.6e-6), moving
//    ~1000 fma-pipe instrs/edge onto the LSU pipe
//  * BN affine fold unchanged: scatter raw h, bn applied on node side
// ---------------------------------------------------------------------------

#define MAX_N 131072
typedef unsigned long long u64;

__device__ float  g_node_acc[MAX_N * 16];
__device__ float  g_degree[MAX_N];
__device__ double g_esum[16], g_esq[16];
__device__ double g_nsum[16], g_nsq[16];
__device__ float  g_es[16], g_et[16];
__device__ float  g_ns[16], g_nt[16];

__device__ __forceinline__ float gelu_exact(float x) {
    return 0.5f * x * (1.0f + erff(x * 0.70710678118654752440f));
}

__device__ __forceinline__ u64 pk2(float a, float b) {
    u64 r; asm("mov.b64 %0, {%1, %2};" : "=l"(r) : "f"(a), "f"(b)); return r;
}
__device__ __forceinline__ void upk2(u64 v, float& a, float& b) {
    asm("mov.b64 {%0, %1}, %2;" : "=f"(a), "=f"(b) : "l"(v));
}
__device__ __forceinline__ u64 fma2(u64 a, u64 b, u64 c) {
    u64 d; asm("fma.rn.f32x2 %0, %1, %2, %3;" : "=l"(d) : "l"(a), "l"(b), "l"(c));
    return d;
}

// ---------------------------------------------------------------------------
__global__ void k_zero(int N) {
    int i = blockIdx.x * blockDim.x + threadIdx.x;
    int tot = N * 16;
    if (i < tot) g_node_acc[i] = 0.0f;
    if (i < N)   g_degree[i]   = 0.0f;
    if (i < 16) {
        g_esum[i] = 0.0; g_esq[i] = 0.0;
        g_nsum[i] = 0.0; g_nsq[i] = 0.0;
    }
}

// ---------------------------------------------------------------------------
// Edge kernel
// ---------------------------------------------------------------------------
__global__ __launch_bounds__(128)
void k_edge(const float* __restrict__ coords,
            const float* __restrict__ normals,
            const float* __restrict__ curv,
            const int* __restrict__ row,
            const int* __restrict__ col,
            const float* __restrict__ W1, const float* __restrict__ b1,
            const float* __restrict__ W2, const float* __restrict__ b2,
            const float* __restrict__ W3, const float* __restrict__ b3,
            int E, int N)
{
    __shared__ u64 sW1d[8 * 64];     //  4 KB, (w,w) duplicated
    __shared__ u64 sW2d[64 * 32];    // 16 KB
    __shared__ u64 sW3d[32 * 16];    //  4 KB
    __shared__ u64 sb1d[64], sb2d[32], sb3d[16];
    __shared__ float2 slut[2048];    // 16 KB gelu lerp table
    __shared__ float redS[4][16], redQ[4][16];

    for (int i = threadIdx.x; i < 512;  i += 128) sW1d[i] = pk2(W1[i], W1[i]);
    for (int i = threadIdx.x; i < 2048; i += 128) sW2d[i] = pk2(W2[i], W2[i]);
    for (int i = threadIdx.x; i < 512;  i += 128) sW3d[i] = pk2(W3[i], W3[i]);
    if (threadIdx.x < 64) sb1d[threadIdx.x] = pk2(b1[threadIdx.x], b1[threadIdx.x]);
    if (threadIdx.x < 32) sb2d[threadIdx.x] = pk2(b2[threadIdx.x], b2[threadIdx.x]);
    if (threadIdx.x < 16) sb3d[threadIdx.x] = pk2(b3[threadIdx.x], b3[threadIdx.x]);
    // gelu LUT: x_i = (i-1024)/128 over [-8, 8), entry = (g(x_i), g(x_{i+1})-g(x_i))
    for (int i = threadIdx.x; i < 2048; i += 128) {
        float x0 = (float)(i - 1024) * 0.0078125f;
        float g0 = gelu_exact(x0);
        float g1 = gelu_exact(x0 + 0.0078125f);
        slut[i] = make_float2(g0, g1 - g0);
    }
    __syncthreads();

    float lsum[16], lsq[16];
#pragma unroll
    for (int k = 0; k < 16; k++) { lsum[k] = 0.0f; lsq[k] = 0.0f; }

    const int P = (E + 1) >> 1;                 // edge pairs
    const int stride = gridDim.x * blockDim.x;
    for (int p = blockIdx.x * blockDim.x + threadIdx.x; p < P; p += stride) {
        const int e0 = 2 * p;
        const bool second = (e0 + 1) < E;
        int r0, c0, r1, c1;
        if (second) {
            int2 rr = *reinterpret_cast<const int2*>(row + e0);
            int2 cc = *reinterpret_cast<const int2*>(col + e0);
            r0 = rr.x; r1 = rr.y; c0 = cc.x; c1 = cc.y;
        } else {
            r0 = row[e0]; c0 = col[e0]; r1 = r0; c1 = c0;
        }
        if ((unsigned)r0 >= (unsigned)N || (unsigned)c0 >= (unsigned)N ||
            (unsigned)r1 >= (unsigned)N || (unsigned)c1 >= (unsigned)N) continue;

        // --- packed geometry (lane x = edge0, lane y = edge1) ---
        u64 prx = pk2(coords[3*r0+0], coords[3*r1+0]);
        u64 pry = pk2(coords[3*r0+1], coords[3*r1+1]);
        u64 prz = pk2(coords[3*r0+2], coords[3*r1+2]);
        u64 pcx = pk2(coords[3*c0+0], coords[3*c1+0]);
        u64 pcy = pk2(coords[3*c0+1], coords[3*c1+1]);
        u64 pcz = pk2(coords[3*c0+2], coords[3*c1+2]);
        u64 nrx = pk2(normals[3*r0+0], normals[3*r1+0]);
        u64 nry = pk2(normals[3*r0+1], normals[3*r1+1]);
        u64 nrz = pk2(normals[3*r0+2], normals[3*r1+2]);
        u64 ncx = pk2(normals[3*c0+0], normals[3*c1+0]);
        u64 ncy = pk2(normals[3*c0+1], normals[3*c1+1]);
        u64 ncz = pk2(normals[3*c0+2], normals[3*c1+2]);

        float ax, bx;
        u64 ef[8];
        // delta (scalar subtract per half: do packed via unpack-free route)
        {
            float a0,a1,b0,b1;
            upk2(pcx,a0,a1); upk2(prx,b0,b1); ef[0] = pk2(a0-b0, a1-b1);
            upk2(pcy,a0,a1); upk2(pry,b0,b1); ef[1] = pk2(a0-b0, a1-b1);
            upk2(pcz,a0,a1); upk2(prz,b0,b1); ef[2] = pk2(a0-b0, a1-b1);
        }
        // normal_dot, cos_row, cos_col — scalar per half (cheap, ~40 ops)
        {
            float dx0,dx1,dy0,dy1,dz0,dz1;
            upk2(ef[0],dx0,dx1); upk2(ef[1],dy0,dy1); upk2(ef[2],dz0,dz1);
            float nrx0,nrx1,nry0,nry1,nrz0,nrz1, ncx0,ncx1,ncy0,ncy1,ncz0,ncz1;
            upk2(nrx,nrx0,nrx1); upk2(nry,nry0,nry1); upk2(nrz,nrz0,nrz1);
            upk2(ncx,ncx0,ncx1); upk2(ncy,ncy0,ncy1); upk2(ncz,ncz0,ncz1);

            float nd0 = nrx0*ncx0 + nry0*ncy0 + nrz0*ncz0;
            float nd1 = nrx1*ncx1 + nry1*ncy1 + nrz1*ncz1;
            ef[3] = pk2(nd0, nd1);

            float dn0 = sqrtf(dx0*dx0 + dy0*dy0 + dz0*dz0) + 1e-8f;
            float dn1 = sqrtf(dx1*dx1 + dy1*dy1 + dz1*dz1) + 1e-8f;
            float iv0 = 1.0f / dn0, iv1 = 1.0f / dn1;
            float cr0 = fminf(1.0f, fmaxf(-1.0f, (nrx0*dx0+nry0*dy0+nrz0*dz0)*iv0));
            float cr1 = fminf(1.0f, fmaxf(-1.0f, (nrx1*dx1+nry1*dy1+nrz1*dz1)*iv1));
            float cc0 = fminf(1.0f, fmaxf(-1.0f, (ncx0*dx0+ncy0*dy0+ncz0*dz0)*iv0));
            float cc1 = fminf(1.0f, fmaxf(-1.0f, (ncx1*dx1+ncy1*dy1+ncz1*dz1)*iv1));
            ef[4] = pk2(cr0, cr1);
            ef[5] = pk2(cc0, cc1);
        }
        ef[6] = pk2(curv[4*c0+0] - curv[4*r0+0], curv[4*c1+0] - curv[4*r1+0]);
        ef[7] = pk2(curv[4*c0+1] - curv[4*r0+1], curv[4*c1+1] - curv[4*r1+1]);

        // --- MLP, fully packed ---
        u64 acc2[32];
#pragma unroll
        for (int j = 0; j < 32; j++) acc2[j] = sb2d[j];

#pragma unroll
        for (int i = 0; i < 64; i++) {
            u64 a = sb1d[i];
#pragma unroll
            for (int k = 0; k < 8; k++) a = fma2(ef[k], sW1d[k*64 + i], a);
            // gelu via LUT (per half)
            upk2(a, ax, bx);
            float ta = fminf(fmaxf(fmaf(ax, 128.0f, 1024.0f), 0.0f), 2046.999f);
            float tb = fminf(fmaxf(fmaf(bx, 128.0f, 1024.0f), 0.0f), 2046.999f);
            int ia = (int)ta, ib = (int)tb;
            float2 ea = slut[ia], eb = slut[ib];
            float ya = fmaf(ta - (float)ia, ea.y, ea.x);
            float yb = fmaf(tb - (float)ib, eb.y, eb.x);
            if (ax > 8.0f) ya = ax;
            if (bx > 8.0f) yb = bx;
            u64 x = pk2(ya, yb);
#pragma unroll
            for (int j = 0; j < 32; j++) acc2[j] = fma2(x, sW2d[i*32 + j], acc2[j]);
        }

        u64 h2[16];
#pragma unroll
        for (int k = 0; k < 16; k++) h2[k] = sb3d[k];
#pragma unroll
        for (int j = 0; j < 32; j++) {
            upk2(acc2[j], ax, bx);
            float ta = fminf(fmaxf(fmaf(ax, 128.0f, 1024.0f), 0.0f), 2046.999f);
            float tb = fminf(fmaxf(fmaf(bx, 128.0f, 1024.0f), 0.0f), 2046.999f);
            int ia = (int)ta, ib = (int)tb;
            float2 ea = slut[ia], eb = slut[ib];
            float ya = fmaf(ta - (float)ia, ea.y, ea.x);
            float yb = fmaf(tb - (float)ib, eb.y, eb.x);
            if (ax > 8.0f) ya = ax;
            if (bx > 8.0f) yb = bx;
            u64 x = pk2(ya, yb);
#pragma unroll
            for (int k = 0; k < 16; k++) h2[k] = fma2(x, sW3d[j*16 + k], h2[k]);
        }

        // --- stats + scatter ---
        float hA[16], hB[16];
#pragma unroll
        for (int k = 0; k < 16; k++) {
            upk2(h2[k], hA[k], hB[k]);
            lsum[k] += hA[k];
            lsq[k]   = fmaf(hA[k], hA[k], lsq[k]);
            if (second) {
                lsum[k] += hB[k];
                lsq[k]   = fmaf(hB[k], hB[k], lsq[k]);
            }
        }

        float4* ar0 = reinterpret_cast<float4*>(&g_node_acc[(size_t)r0 * 16]);
        float4* ac0 = reinterpret_cast<float4*>(&g_node_acc[(size_t)c0 * 16]);
#pragma unroll
        for (int q = 0; q < 4; q++) {
            float4 v = make_float4(hA[4*q+0], hA[4*q+1], hA[4*q+2], hA[4*q+3]);
            atomicAdd(ar0 + q, v);
            atomicAdd(ac0 + q, v);
        }
        atomicAdd(&g_degree[r0], 1.0f);
        atomicAdd(&g_degree[c0], 1.0f);

        if (second) {
            float4* ar1 = reinterpret_cast<float4*>(&g_node_acc[(size_t)r1 * 16]);
            float4* ac1 = reinterpret_cast<float4*>(&g_node_acc[(size_t)c1 * 16]);
#pragma unroll
            for (int q = 0; q < 4; q++) {
                float4 v = make_float4(hB[4*q+0], hB[4*q+1], hB[4*q+2], hB[4*q+3]);
                atomicAdd(ar1 + q, v);
                atomicAdd(ac1 + q, v);
            }
            atomicAdd(&g_degree[r1], 1.0f);
            atomicAdd(&g_degree[c1], 1.0f);
        }
    }

    // block-level BN-stat reduction
#pragma unroll
    for (int k = 0; k < 16; k++) {
        float s = lsum[k], q = lsq[k];
#pragma unroll
        for (int o = 16; o > 0; o >>= 1) {
            s += __shfl_xor_sync(0xffffffffu, s, o);
            q += __shfl_xor_sync(0xffffffffu, q, o);
        }
        if ((threadIdx.x & 31) == 0) {
            redS[threadIdx.x >> 5][k] = s;
            redQ[threadIdx.x >> 5][k] = q;
        }
    }
    __syncthreads();
    if (threadIdx.x < 16) {
        double s = 0.0, q = 0.0;
#pragma unroll
        for (int w = 0; w < 4; w++) { s += (double)redS[w][threadIdx.x];
                                      q += (double)redQ[w][threadIdx.x]; }
        atomicAdd(&g_esum[threadIdx.x], s);
        atomicAdd(&g_esq[threadIdx.x],  q);
    }
}

// ---------------------------------------------------------------------------
__global__ void k_ecoef(const float* __restrict__ g, const float* __restrict__ b,
                        int E)
{
    int j = threadIdx.x;
    if (j < 16) {
        double invE = 1.0 / (double)E;
        double m = g_esum[j] * invE;
        double v = g_esq[j] * invE - m * m;
        double s = (double)g[j] / sqrt(v + 1e-5);
        g_es[j] = (float)s;
        g_et[j] = (float)((double)b[j] - m * s);
    }
}

// ---------------------------------------------------------------------------
__global__ __launch_bounds__(256)
void k_node(const float* __restrict__ Wp, const float* __restrict__ bp,
            int N, float* __restrict__ out)
{
    __shared__ float sWp[256], sbp[16], ses[16], set_[16];
    __shared__ float redS[8][16], redQ[8][16];
    if (threadIdx.x < 256) sWp[threadIdx.x] = Wp[threadIdx.x];
    if (threadIdx.x < 16) {
        sbp[threadIdx.x]  = bp[threadIdx.x];
        ses[threadIdx.x]  = g_es[threadIdx.x];
        set_[threadIdx.x] = g_et[threadIdx.x];
    }
    __syncthreads();

    float lsum[16], lsq[16];
#pragma unroll
    for (int k = 0; k < 16; k++) { lsum[k] = 0.0f; lsq[k] = 0.0f; }

    const int n = blockIdx.x * blockDim.x + threadIdx.x;
    if (n < N) {
        const float deg  = g_degree[n];
        const float invd = 1.0f / fmaxf(deg, 1.0f);
        float pre[16];
#pragma unroll
        for (int j = 0; j < 16; j++) {
            const float a = g_node_acc[n * 16 + j];
            pre[j] = (ses[j] * a + set_[j] * deg) * invd;
        }
        float y[16];
#pragma unroll
        for (int k = 0; k < 16; k++) y[k] = sbp[k];
#pragma unroll
        for (int j = 0; j < 16; j++)
#pragma unroll
            for (int k = 0; k < 16; k++) y[k] = fmaf(pre[j], sWp[j*16 + k], y[k]);
#pragma unroll
        for (int k = 0; k < 16; k++) {
            out[n * 16 + k] = y[k];
            lsum[k] = y[k];
            lsq[k]  = y[k] * y[k];
        }
    }

#pragma unroll
    for (int k = 0; k < 16; k++) {
        float s = lsum[k], q = lsq[k];
#pragma unroll
        for (int o = 16; o > 0; o >>= 1) {
            s += __shfl_xor_sync(0xffffffffu, s, o);
            q += __shfl_xor_sync(0xffffffffu, q, o);
        }
        if ((threadIdx.x & 31) == 0) {
            redS[threadIdx.x >> 5][k] = s;
            redQ[threadIdx.x >> 5][k] = q;
        }
    }
    __syncthreads();
    if (threadIdx.x < 16) {
        double s = 0.0, q = 0.0;
#pragma unroll
        for (int w = 0; w < 8; w++) { s += (double)redS[w][threadIdx.x];
                                      q += (double)redQ[w][threadIdx.x]; }
        atomicAdd(&g_nsum[threadIdx.x], s);
        atomicAdd(&g_nsq[threadIdx.x],  q);
    }
}

// ---------------------------------------------------------------------------
__global__ void k_ncoef(const float* __restrict__ g, const float* __restrict__ b,
                        int N)
{
    int j = threadIdx.x;
    if (j < 16) {
        double invN = 1.0 / (double)N;
        double m = g_nsum[j] * invN;
        double v = g_nsq[j] * invN - m * m;
        double s = (double)g[j] / sqrt(v + 1e-5);
        g_ns[j] = (float)s;
        g_nt[j] = (float)((double)b[j] - m * s);
    }
}

// ---------------------------------------------------------------------------
__global__ void k_norm(float* __restrict__ out, int total)
{
    int i = blockIdx.x * blockDim.x + threadIdx.x;
    if (i < total) {
        int j = i & 15;
        out[i] = fmaf(out[i], g_ns[j], g_nt[j]);
    }
}

// ---------------------------------------------------------------------------
extern "C" void kernel_launch(void* const* d_in, const int* in_sizes, int n_in,
                              void* d_out, int out_size)
{
    const float* coords  = (const float*)d_in[0];
    const float* normals = (const float*)d_in[1];
    const float* curv    = (const float*)d_in[2];
    const int*   ei      = (const int*)d_in[3];
    const float* W1 = (const float*)d_in[4];
    const float* b1 = (const float*)d_in[5];
    const float* W2 = (const float*)d_in[6];
    const float* b2 = (const float*)d_in[7];
    const float* W3 = (const float*)d_in[8];
    const float* b3 = (const float*)d_in[9];
    const float* Wp = (const float*)d_in[10];
    const float* bp = (const float*)d_in[11];
    const float* beg = (const float*)d_in[12];
    const float* beb = (const float*)d_in[13];
    const float* bng = (const float*)d_in[14];
    const float* bnb = (const float*)d_in[15];

    const int N = in_sizes[0] / 3;
    const int E = in_sizes[3] / 2;
    const int* row = ei;
    const int* col = ei + E;
    float* out = (float*)d_out;

    k_zero<<<(N * 16 + 255) / 256, 256>>>(N);
    k_edge<<<2368, 128>>>(coords, normals, curv, row, col,
                          W1, b1, W2, b2, W3, b3, E, N);
    k_ecoef<<<1, 32>>>(beg, beb, E);
    k_node<<<(N + 255) / 256, 256>>>(Wp, bp, N, out);
    k_ncoef<<<1, 32>>>(bng, bnb, N);
    k_norm<<<(N * 16 + 255) / 256, 256>>>(out, N * 16);
}

// round 4
// speedup vs baseline: 1.3724x; 1.3612x over previous
#include <cuda_runtime.h>
#include <cuda_bf16.h>
#include <cstdint>

// ---------------------------------------------------------------------------
// GPUManifoldFeatureEncoder — round 4: tensor-core edge MLP
//   * mma.sync.m16n8k8 tf32 with 3-term split (AhBh+AlBh+AhBl) ~= fp32
//   * weights pre-split into fragment order in smem (1 LDS.128 / MMA triple)
//   * gelu via lerp LUT on register fragments
//   * BN affine fold unchanged: scatter raw h, bn applied node-side
// ---------------------------------------------------------------------------

#define MAX_N 131072
typedef uint32_t u32;

__device__ float  g_node_acc[MAX_N * 16];
__device__ float  g_degree[MAX_N];
__device__ double g_esum[16], g_esq[16];
__device__ double g_nsum[16], g_nsq[16];
__device__ float  g_es[16], g_et[16];
__device__ float  g_ns[16], g_nt[16];

__device__ __forceinline__ float gelu_exact(float x) {
    return 0.5f * x * (1.0f + erff(x * 0.70710678118654752440f));
}

__device__ __forceinline__ u32 tf32_of(float x) {
    u32 r; asm("cvt.rna.tf32.f32 %0, %1;" : "=r"(r) : "f"(x)); return r;
}
__device__ __forceinline__ void split_tf32(float x, u32& hi, u32& lo) {
    asm("cvt.rna.tf32.f32 %0, %1;" : "=r"(hi) : "f"(x));
    float rem = x - __uint_as_float(hi);
    asm("cvt.rna.tf32.f32 %0, %1;" : "=r"(lo) : "f"(rem));
}
__device__ __forceinline__ void mma_tf32(float& d0, float& d1, float& d2, float& d3,
                                         u32 a0, u32 a1, u32 a2, u32 a3,
                                         u32 b0, u32 b1) {
    asm("mma.sync.aligned.m16n8k8.row.col.f32.tf32.tf32.f32 "
        "{%0,%1,%2,%3}, {%4,%5,%6,%7}, {%8,%9}, {%0,%1,%2,%3};"
        : "+f"(d0), "+f"(d1), "+f"(d2), "+f"(d3)
        : "r"(a0), "r"(a1), "r"(a2), "r"(a3), "r"(b0), "r"(b1));
}

// ---------------------------------------------------------------------------
__global__ void k_zero(int N) {
    int i = blockIdx.x * blockDim.x + threadIdx.x;
    int tot = N * 16;
    if (i < tot) g_node_acc[i] = 0.0f;
    if (i < N)   g_degree[i]   = 0.0f;
    if (i < 16) {
        g_esum[i] = 0.0; g_esq[i] = 0.0;
        g_nsum[i] = 0.0; g_nsq[i] = 0.0;
    }
}

// ---------------------------------------------------------------------------
// smem layout (floats):
//  sW1f : 8nt * 32 * 4            = 1024   (float4 frag: bh0,bh1,bl0,bl1)
//  sW2f : 32combo * 32 * 4        = 4096
//  sW3f : 8combo * 32 * 4         = 1024
//  sb   : 128 (b1[64], b2[32], b3[16], pad)
//  lut  : 2048 float2             = 4096
//  per-warp staging: ef 32*8=256, h1s 16*68=1088, h2s 16*36=576  -> 1920
// ---------------------------------------------------------------------------
#define OFF_W1   0
#define OFF_W2   1024
#define OFF_W3   5120
#define OFF_B1   6144
#define OFF_B2   6208
#define OFF_B3   6240
#define OFF_LUT  6272
#define OFF_WARP 10368
#define WARP_FLOATS 1920
#define H1_PAD 68
#define H2_PAD 36
#define OUT_PAD 20

__global__ __launch_bounds__(256)
void k_edge(const float* __restrict__ coords,
            const float* __restrict__ normals,
            const float* __restrict__ curv,
            const int* __restrict__ rowi,
            const int* __restrict__ coli,
            const float* __restrict__ W1, const float* __restrict__ b1,
            const float* __restrict__ W2, const float* __restrict__ b2,
            const float* __restrict__ W3, const float* __restrict__ b3,
            int E, int N)
{
    extern __shared__ float sm[];
    float4* sW1f = reinterpret_cast<float4*>(sm + OFF_W1);
    float4* sW2f = reinterpret_cast<float4*>(sm + OFF_W2);
    float4* sW3f = reinterpret_cast<float4*>(sm + OFF_W3);
    float*  sb1  = sm + OFF_B1;
    float*  sb2  = sm + OFF_B2;
    float*  sb3  = sm + OFF_B3;
    float2* slut = reinterpret_cast<float2*>(sm + OFF_LUT);

    const int tid  = threadIdx.x;
    const int lane = tid & 31;
    const int wid  = tid >> 5;
    const int g    = lane >> 2;   // groupID 0..7
    const int j    = lane & 3;    // threadID in group

    // ---- preamble: weight fragments (tf32 hi/lo), biases, gelu LUT ----
    // frag for combo (ks,nt), lane t: bh0=tf32(W[ks*8+t%4][nt*8+t/4]),
    // bh1 = same with k+4; bl* = residuals.
    for (int idx = tid; idx < 8 * 32; idx += 256) {        // W1: 1 kstep, 8 nt
        int nt = idx >> 5, t = idx & 31;
        int kk = t & 3, nn = nt * 8 + (t >> 2);
        float w0 = W1[kk * 64 + nn], w1 = W1[(kk + 4) * 64 + nn];
        u32 h0, l0, h1_, l1; split_tf32(w0, h0, l0); split_tf32(w1, h1_, l1);
        sW1f[idx] = make_float4(__uint_as_float(h0), __uint_as_float(h1_),
                                __uint_as_float(l0), __uint_as_float(l1));
    }
    for (int idx = tid; idx < 32 * 32; idx += 256) {       // W2: 8 ks x 4 nt
        int combo = idx >> 5, t = idx & 31;
        int ks = combo >> 2, nt = combo & 3;
        int kk = ks * 8 + (t & 3), nn = nt * 8 + (t >> 2);
        float w0 = W2[kk * 32 + nn], w1 = W2[(kk + 4) * 32 + nn];
        u32 h0, l0, h1_, l1; split_tf32(w0, h0, l0); split_tf32(w1, h1_, l1);
        sW2f[idx] = make_float4(__uint_as_float(h0), __uint_as_float(h1_),
                                __uint_as_float(l0), __uint_as_float(l1));
    }
    for (int idx = tid; idx < 8 * 32; idx += 256) {        // W3: 4 ks x 2 nt
        int combo = idx >> 5, t = idx & 31;
        int ks = combo >> 1, nt = combo & 1;
        int kk = ks * 8 + (t & 3), nn = nt * 8 + (t >> 2);
        float w0 = W3[kk * 16 + nn], w1 = W3[(kk + 4) * 16 + nn];
        u32 h0, l0, h1_, l1; split_tf32(w0, h0, l0); split_tf32(w1, h1_, l1);
        sW3f[idx] = make_float4(__uint_as_float(h0), __uint_as_float(h1_),
                                __uint_as_float(l0), __uint_as_float(l1));
    }
    if (tid < 64) sb1[tid] = b1[tid];
    if (tid < 32) sb2[tid] = b2[tid];
    if (tid < 16) sb3[tid] = b3[tid];
    for (int i = tid; i < 2048; i += 256) {
        float x0 = (float)(i - 1024) * 0.0078125f;
        float g0 = gelu_exact(x0);
        slut[i] = make_float2(g0, gelu_exact(x0 + 0.0078125f) - g0);
    }
    __syncthreads();

    float* efs = sm + OFF_WARP + wid * WARP_FLOATS;   // [32][8]
    float* h1s = efs + 256;                           // [16][68]
    float* h2s = h1s + 1088;                          // [16][36]
    float* outs = h1s;                                // reuse as [16][20]
    float4* outs4 = reinterpret_cast<float4*>(outs);

    float lsum4[4] = {0, 0, 0, 0}, lsq4[4] = {0, 0, 0, 0};

    const int tiles32 = (E + 31) >> 5;
    const int warpsTotal = gridDim.x * 8;
    const int warpGlobal = blockIdx.x * 8 + wid;

    for (int tb32 = warpGlobal; tb32 < tiles32; tb32 += warpsTotal) {
        const int ebase = tb32 << 5;
        const int e = ebase + lane;
        const bool ev = (e < E);

        // ---- geometry per lane ----
        int r = ev ? rowi[e] : 0;
        int c = ev ? coli[e] : 0;
        if ((unsigned)r >= (unsigned)N) r = 0;
        if ((unsigned)c >= (unsigned)N) c = 0;

        {
            const float dx = coords[3*c+0] - coords[3*r+0];
            const float dy = coords[3*c+1] - coords[3*r+1];
            const float dz = coords[3*c+2] - coords[3*r+2];
            const float nrx = normals[3*r+0], nry = normals[3*r+1], nrz = normals[3*r+2];
            const float ncx = normals[3*c+0], ncy = normals[3*c+1], ncz = normals[3*c+2];
            const float ndot = nrx*ncx + nry*ncy + nrz*ncz;
            const float dn = sqrtf(dx*dx + dy*dy + dz*dz) + 1e-8f;
            const float inv = 1.0f / dn;
            float cr = fminf(1.0f, fmaxf(-1.0f, (nrx*dx+nry*dy+nrz*dz)*inv));
            float cc = fminf(1.0f, fmaxf(-1.0f, (ncx*dx+ncy*dy+ncz*dz)*inv));
            float* er = efs + lane * 8;
            er[0] = dx; er[1] = dy; er[2] = dz; er[3] = ndot;
            er[4] = cr; er[5] = cc;
            er[6] = curv[4*c+0] - curv[4*r+0];
            er[7] = curv[4*c+1] - curv[4*r+1];
        }
        __syncwarp();

        // ---- two 16-edge MMA tiles ----
#pragma unroll
        for (int t = 0; t < 2; t++) {
            const int tb = ebase + t * 16;

            // Layer 1: [16,8] @ [8,64]
            u32 ah[4], al[4];
            {
                const float* base = efs + t * 128;
                split_tf32(base[(g    )*8 + j    ], ah[0], al[0]);
                split_tf32(base[(g + 8)*8 + j    ], ah[1], al[1]);
                split_tf32(base[(g    )*8 + j + 4], ah[2], al[2]);
                split_tf32(base[(g + 8)*8 + j + 4], ah[3], al[3]);
            }
            float d1v[8][4];
#pragma unroll
            for (int nt = 0; nt < 8; nt++) {
                d1v[nt][0] = d1v[nt][1] = d1v[nt][2] = d1v[nt][3] = 0.0f;
                float4 bw = sW1f[nt * 32 + lane];
                u32 bh0 = __float_as_uint(bw.x), bh1 = __float_as_uint(bw.y);
                u32 bl0 = __float_as_uint(bw.z), bl1 = __float_as_uint(bw.w);
                mma_tf32(d1v[nt][0], d1v[nt][1], d1v[nt][2], d1v[nt][3],
                         ah[0], ah[1], ah[2], ah[3], bh0, bh1);
                mma_tf32(d1v[nt][0], d1v[nt][1], d1v[nt][2], d1v[nt][3],
                         al[0], al[1], al[2], al[3], bh0, bh1);
                mma_tf32(d1v[nt][0], d1v[nt][1], d1v[nt][2], d1v[nt][3],
                         ah[0], ah[1], ah[2], ah[3], bl0, bl1);
            }
            // bias + gelu + stage h1 [16][68]
#pragma unroll
            for (int nt = 0; nt < 8; nt++) {
                const int cb = nt * 8 + 2 * j;
                const float bx = sb1[cb], by = sb1[cb + 1];
#pragma unroll
                for (int hrow = 0; hrow < 2; hrow++) {
                    float v0 = d1v[nt][2*hrow]     + bx;
                    float v1 = d1v[nt][2*hrow + 1] + by;
                    float t0 = fminf(fmaxf(fmaf(v0, 128.0f, 1024.0f), 0.0f), 2046.999f);
                    float t1 = fminf(fmaxf(fmaf(v1, 128.0f, 1024.0f), 0.0f), 2046.999f);
                    int i0 = (int)t0, i1 = (int)t1;
                    float2 e0 = slut[i0], e1 = slut[i1];
                    float y0 = fmaf(t0 - (float)i0, e0.y, e0.x);
                    float y1 = fmaf(t1 - (float)i1, e1.y, e1.x);
                    if (v0 > 8.0f) y0 = v0;
                    if (v1 > 8.0f) y1 = v1;
                    const int rr = g + 8 * hrow;
                    *reinterpret_cast<float2*>(h1s + rr * H1_PAD + cb) =
                        make_float2(y0, y1);
                }
            }
            __syncwarp();

            // Layer 2: [16,64] @ [64,32]
            float d2v[4][4];
#pragma unroll
            for (int nt = 0; nt < 4; nt++)
                d2v[nt][0] = d2v[nt][1] = d2v[nt][2] = d2v[nt][3] = 0.0f;
#pragma unroll
            for (int ks = 0; ks < 8; ks++) {
                const int cbk = ks * 8;
                split_tf32(h1s[(g    )*H1_PAD + cbk + j    ], ah[0], al[0]);
                split_tf32(h1s[(g + 8)*H1_PAD + cbk + j    ], ah[1], al[1]);
                split_tf32(h1s[(g    )*H1_PAD + cbk + j + 4], ah[2], al[2]);
                split_tf32(h1s[(g + 8)*H1_PAD + cbk + j + 4], ah[3], al[3]);
#pragma unroll
                for (int nt = 0; nt < 4; nt++) {
                    float4 bw = sW2f[(ks * 4 + nt) * 32 + lane];
                    u32 bh0 = __float_as_uint(bw.x), bh1 = __float_as_uint(bw.y);
                    u32 bl0 = __float_as_uint(bw.z), bl1 = __float_as_uint(bw.w);
                    mma_tf32(d2v[nt][0], d2v[nt][1], d2v[nt][2], d2v[nt][3],
                             ah[0], ah[1], ah[2], ah[3], bh0, bh1);
                    mma_tf32(d2v[nt][0], d2v[nt][1], d2v[nt][2], d2v[nt][3],
                             al[0], al[1], al[2], al[3], bh0, bh1);
                    mma_tf32(d2v[nt][0], d2v[nt][1], d2v[nt][2], d2v[nt][3],
                             ah[0], ah[1], ah[2], ah[3], bl0, bl1);
                }
            }
#pragma unroll
            for (int nt = 0; nt < 4; nt++) {
                const int cb = nt * 8 + 2 * j;
                const float bx = sb2[cb], by = sb2[cb + 1];
#pragma unroll
                for (int hrow = 0; hrow < 2; hrow++) {
                    float v0 = d2v[nt][2*hrow]     + bx;
                    float v1 = d2v[nt][2*hrow + 1] + by;
                    float t0 = fminf(fmaxf(fmaf(v0, 128.0f, 1024.0f), 0.0f), 2046.999f);
                    float t1 = fminf(fmaxf(fmaf(v1, 128.0f, 1024.0f), 0.0f), 2046.999f);
                    int i0 = (int)t0, i1 = (int)t1;
                    float2 e0 = slut[i0], e1 = slut[i1];
                    float y0 = fmaf(t0 - (float)i0, e0.y, e0.x);
                    float y1 = fmaf(t1 - (float)i1, e1.y, e1.x);
                    if (v0 > 8.0f) y0 = v0;
                    if (v1 > 8.0f) y1 = v1;
                    const int rr = g + 8 * hrow;
                    *reinterpret_cast<float2*>(h2s + rr * H2_PAD + cb) =
                        make_float2(y0, y1);
                }
            }
            __syncwarp();

            // Layer 3: [16,32] @ [32,16]
            float d3v[2][4];
#pragma unroll
            for (int nt = 0; nt < 2; nt++)
                d3v[nt][0] = d3v[nt][1] = d3v[nt][2] = d3v[nt][3] = 0.0f;
#pragma unroll
            for (int ks = 0; ks < 4; ks++) {
                const int cbk = ks * 8;
                split_tf32(h2s[(g    )*H2_PAD + cbk + j    ], ah[0], al[0]);
                split_tf32(h2s[(g + 8)*H2_PAD + cbk + j    ], ah[1], al[1]);
                split_tf32(h2s[(g    )*H2_PAD + cbk + j + 4], ah[2], al[2]);
                split_tf32(h2s[(g + 8)*H2_PAD + cbk + j + 4], ah[3], al[3]);
#pragma unroll
                for (int nt = 0; nt < 2; nt++) {
                    float4 bw = sW3f[(ks * 2 + nt) * 32 + lane];
                    u32 bh0 = __float_as_uint(bw.x), bh1 = __float_as_uint(bw.y);
                    u32 bl0 = __float_as_uint(bw.z), bl1 = __float_as_uint(bw.w);
                    mma_tf32(d3v[nt][0], d3v[nt][1], d3v[nt][2], d3v[nt][3],
                             ah[0], ah[1], ah[2], ah[3], bh0, bh1);
                    mma_tf32(d3v[nt][0], d3v[nt][1], d3v[nt][2], d3v[nt][3],
                             al[0], al[1], al[2], al[3], bh0, bh1);
                    mma_tf32(d3v[nt][0], d3v[nt][1], d3v[nt][2], d3v[nt][3],
                             ah[0], ah[1], ah[2], ah[3], bl0, bl1);
                }
            }
            __syncwarp();   // all lanes done reading h2s/outs region conflicts

            // bias + stats + stage out [16][20]
            const bool fullTile = (tb + 16 <= E);
#pragma unroll
            for (int nt = 0; nt < 2; nt++) {
                const int cb = nt * 8 + 2 * j;
                const float bx = sb3[cb], by = sb3[cb + 1];
#pragma unroll
                for (int hrow = 0; hrow < 2; hrow++) {
                    float v0 = d3v[nt][2*hrow]     + bx;
                    float v1 = d3v[nt][2*hrow + 1] + by;
                    const int rr = g + 8 * hrow;
                    if (fullTile || (tb + rr < E)) {
                        lsum4[nt*2+0] += v0;
                        lsum4[nt*2+1] += v1;
                        lsq4[nt*2+0]   = fmaf(v0, v0, lsq4[nt*2+0]);
                        lsq4[nt*2+1]   = fmaf(v1, v1, lsq4[nt*2+1]);
                    }
                    *reinterpret_cast<float2*>(outs + rr * OUT_PAD + cb) =
                        make_float2(v0, v1);
                }
            }
            __syncwarp();

            // scatter: lanes 0-15 -> row endpoint, 16-31 -> col endpoint
            {
                const int le = lane & 15;
                const int src = t * 16 + le;
                const int rr = __shfl_sync(0xffffffffu, r, src);
                const int cc = __shfl_sync(0xffffffffu, c, src);
                if (tb + le < E) {
                    const int node = (lane < 16) ? rr : cc;
                    float4* dst = reinterpret_cast<float4*>(
                        &g_node_acc[(size_t)node * 16]);
#pragma unroll
                    for (int q = 0; q < 4; q++)
                        atomicAdd(dst + q, outs4[le * 5 + q]);
                    atomicAdd(&g_degree[node], 1.0f);
                }
            }
            __syncwarp();   // outs (==h1s) will be rewritten next tile
        }
    }

    // ---- BN-stat reduction: classes share j = lane&3 ----
#pragma unroll
    for (int i = 0; i < 4; i++) {
#pragma unroll
        for (int o = 4; o < 32; o <<= 1) {
            lsum4[i] += __shfl_xor_sync(0xffffffffu, lsum4[i], o);
            lsq4[i]  += __shfl_xor_sync(0xffffffffu, lsq4[i],  o);
        }
    }
    if (lane < 4) {
#pragma unroll
        for (int i = 0; i < 4; i++) {
            const int col = (i >> 1) * 8 + 2 * lane + (i & 1);
            atomicAdd(&g_esum[col], (double)lsum4[i]);
            atomicAdd(&g_esq[col],  (double)lsq4[i]);
        }
    }
}

// ---------------------------------------------------------------------------
__global__ void k_ecoef(const float* __restrict__ g, const float* __restrict__ b,
                        int E)
{
    int j = threadIdx.x;
    if (j < 16) {
        double invE = 1.0 / (double)E;
        double m = g_esum[j] * invE;
        double v = g_esq[j] * invE - m * m;
        double s = (double)g[j] / sqrt(v + 1e-5);
        g_es[j] = (float)s;
        g_et[j] = (float)((double)b[j] - m * s);
    }
}

// ---------------------------------------------------------------------------
__global__ __launch_bounds__(256)
void k_node(const float* __restrict__ Wp, const float* __restrict__ bp,
            int N, float* __restrict__ out)
{
    __shared__ float sWp[256], sbp[16], ses[16], set_[16];
    __shared__ float redS[8][16], redQ[8][16];
    if (threadIdx.x < 256) sWp[threadIdx.x] = Wp[threadIdx.x];
    if (threadIdx.x < 16) {
        sbp[threadIdx.x]  = bp[threadIdx.x];
        ses[threadIdx.x]  = g_es[threadIdx.x];
        set_[threadIdx.x] = g_et[threadIdx.x];
    }
    __syncthreads();

    float lsum[16], lsq[16];
#pragma unroll
    for (int k = 0; k < 16; k++) { lsum[k] = 0.0f; lsq[k] = 0.0f; }

    const int n = blockIdx.x * blockDim.x + threadIdx.x;
    if (n < N) {
        const float deg  = g_degree[n];
        const float invd = 1.0f / fmaxf(deg, 1.0f);
        float pre[16];
#pragma unroll
        for (int j = 0; j < 16; j++) {
            const float a = g_node_acc[n * 16 + j];
            pre[j] = (ses[j] * a + set_[j] * deg) * invd;
        }
        float y[16];
#pragma unroll
        for (int k = 0; k < 16; k++) y[k] = sbp[k];
#pragma unroll
        for (int j = 0; j < 16; j++)
#pragma unroll
            for (int k = 0; k < 16; k++) y[k] = fmaf(pre[j], sWp[j*16 + k], y[k]);
#pragma unroll
        for (int k = 0; k < 16; k++) {
            out[n * 16 + k] = y[k];
            lsum[k] = y[k];
            lsq[k]  = y[k] * y[k];
        }
    }

#pragma unroll
    for (int k = 0; k < 16; k++) {
        float s = lsum[k], q = lsq[k];
#pragma unroll
        for (int o = 16; o > 0; o >>= 1) {
            s += __shfl_xor_sync(0xffffffffu, s, o);
            q += __shfl_xor_sync(0xffffffffu, q, o);
        }
        if ((threadIdx.x & 31) == 0) {
            redS[threadIdx.x >> 5][k] = s;
            redQ[threadIdx.x >> 5][k] = q;
        }
    }
    __syncthreads();
    if (threadIdx.x < 16) {
        double s = 0.0, q = 0.0;
#pragma unroll
        for (int w = 0; w < 8; w++) { s += (double)redS[w][threadIdx.x];
                                      q += (double)redQ[w][threadIdx.x]; }
        atomicAdd(&g_nsum[threadIdx.x], s);
        atomicAdd(&g_nsq[threadIdx.x],  q);
    }
}

// ---------------------------------------------------------------------------
__global__ void k_ncoef(const float* __restrict__ g, const float* __restrict__ b,
                        int N)
{
    int j = threadIdx.x;
    if (j < 16) {
        double invN = 1.0 / (double)N;
        double m = g_nsum[j] * invN;
        double v = g_nsq[j] * invN - m * m;
        double s = (double)g[j] / sqrt(v + 1e-5);
        g_ns[j] = (float)s;
        g_nt[j] = (float)((double)b[j] - m * s);
    }
}

// ---------------------------------------------------------------------------
__global__ void k_norm(float* __restrict__ out, int total)
{
    int i = blockIdx.x * blockDim.x + threadIdx.x;
    if (i < total) {
        int j = i & 15;
        out[i] = fmaf(out[i], g_ns[j], g_nt[j]);
    }
}

// ---------------------------------------------------------------------------
extern "C" void kernel_launch(void* const* d_in, const int* in_sizes, int n_in,
                              void* d_out, int out_size)
{
    const float* coords  = (const float*)d_in[0];
    const float* normals = (const float*)d_in[1];
    const float* curv    = (const float*)d_in[2];
    const int*   ei      = (const int*)d_in[3];
    const float* W1 = (const float*)d_in[4];
    const float* b1 = (const float*)d_in[5];
    const float* W2 = (const float*)d_in[6];
    const float* b2 = (const float*)d_in[7];
    const float* W3 = (const float*)d_in[8];
    const float* b3 = (const float*)d_in[9];
    const float* Wp = (const float*)d_in[10];
    const float* bp = (const float*)d_in[11];
    const float* beg = (const float*)d_in[12];
    const float* beb = (const float*)d_in[13];
    const float* bng = (const float*)d_in[14];
    const float* bnb = (const float*)d_in[15];

    const int N = in_sizes[0] / 3;
    const int E = in_sizes[3] / 2;
    const int* row = ei;
    const int* col = ei + E;
    float* out = (float*)d_out;

    const int smemBytes = (OFF_WARP + 8 * WARP_FLOATS) * 4;   // ~101.5 KB
    static bool attrSet = false;
    if (!attrSet) {
        cudaFuncSetAttribute(k_edge, cudaFuncAttributeMaxDynamicSharedMemorySize,
                             smemBytes);
        attrSet = true;
    }

    k_zero<<<(N * 16 + 255) / 256, 256>>>(N);
    k_edge<<<296, 256, smemBytes>>>(coords, normals, curv, row, col,
                                    W1, b1, W2, b2, W3, b3, E, N);
    k_ecoef<<<1, 32>>>(beg, beb, E);
    k_node<<<(N + 255) / 256, 256>>>(Wp, bp, N, out);
    k_ncoef<<<1, 32>>>(bng, bnb, N);
    k_norm<<<(N * 16 + 255) / 256, 256>>>(out, N * 16);
}

// round 5
// speedup vs baseline: 1.5308x; 1.1155x over previous
#include <cuda_runtime.h>
#include <cuda_bf16.h>
#include <cstdint>

// ---------------------------------------------------------------------------
// GPUManifoldFeatureEncoder — round 5:
//   * node features pre-packed [N][8] -> 2x LDG.128 per endpoint gather
//   * 2-term tf32 MMA: act(single tf32) x weight(hi+lo)  (err ~1e-4 << 1e-3)
//   * gelu lerp LUT, BN affine fold, float4 RED scatter (unchanged)
// ---------------------------------------------------------------------------

#define MAX_N 131072
typedef uint32_t u32;

__device__ float  g_nodepack[MAX_N * 8];    // x,y,z,nx | ny,nz,c0,c1
__device__ float  g_node_acc[MAX_N * 16];
__device__ float  g_degree[MAX_N];
__device__ double g_esum[16], g_esq[16];
__device__ double g_nsum[16], g_nsq[16];
__device__ float  g_es[16], g_et[16];
__device__ float  g_ns[16], g_nt[16];

__device__ __forceinline__ float gelu_exact(float x) {
    return 0.5f * x * (1.0f + erff(x * 0.70710678118654752440f));
}
__device__ __forceinline__ u32 tf32_of(float x) {
    u32 r; asm("cvt.rna.tf32.f32 %0, %1;" : "=r"(r) : "f"(x)); return r;
}
__device__ __forceinline__ void split_tf32(float x, u32& hi, u32& lo) {
    asm("cvt.rna.tf32.f32 %0, %1;" : "=r"(hi) : "f"(x));
    float rem = x - __uint_as_float(hi);
    asm("cvt.rna.tf32.f32 %0, %1;" : "=r"(lo) : "f"(rem));
}
__device__ __forceinline__ void mma_tf32(float& d0, float& d1, float& d2, float& d3,
                                         u32 a0, u32 a1, u32 a2, u32 a3,
                                         u32 b0, u32 b1) {
    asm("mma.sync.aligned.m16n8k8.row.col.f32.tf32.tf32.f32 "
        "{%0,%1,%2,%3}, {%4,%5,%6,%7}, {%8,%9}, {%0,%1,%2,%3};"
        : "+f"(d0), "+f"(d1), "+f"(d2), "+f"(d3)
        : "r"(a0), "r"(a1), "r"(a2), "r"(a3), "r"(b0), "r"(b1));
}

// ---------------------------------------------------------------------------
__global__ void k_zero(int N) {
    int i = blockIdx.x * blockDim.x + threadIdx.x;
    int tot = N * 16;
    if (i < tot) g_node_acc[i] = 0.0f;
    if (i < N)   g_degree[i]   = 0.0f;
    if (i < 16) {
        g_esum[i] = 0.0; g_esq[i] = 0.0;
        g_nsum[i] = 0.0; g_nsq[i] = 0.0;
    }
}

__global__ void k_pack(const float* __restrict__ coords,
                       const float* __restrict__ normals,
                       const float* __restrict__ curv, int N)
{
    int n = blockIdx.x * blockDim.x + threadIdx.x;
    if (n < N) {
        float4 a = make_float4(coords[3*n+0], coords[3*n+1], coords[3*n+2],
                               normals[3*n+0]);
        float4 b = make_float4(normals[3*n+1], normals[3*n+2],
                               curv[4*n+0], curv[4*n+1]);
        *reinterpret_cast<float4*>(&g_nodepack[8*n])     = a;
        *reinterpret_cast<float4*>(&g_nodepack[8*n + 4]) = b;
    }
}

// ---------------------------------------------------------------------------
#define OFF_W1   0
#define OFF_W2   1024
#define OFF_W3   5120
#define OFF_B1   6144
#define OFF_B2   6208
#define OFF_B3   6240
#define OFF_LUT  6272
#define OFF_WARP 10368
#define WARP_FLOATS 1920
#define H1_PAD 68
#define H2_PAD 36
#define OUT_PAD 20

__global__ __launch_bounds__(256)
void k_edge(const int* __restrict__ rowi,
            const int* __restrict__ coli,
            const float* __restrict__ W1, const float* __restrict__ b1,
            const float* __restrict__ W2, const float* __restrict__ b2,
            const float* __restrict__ W3, const float* __restrict__ b3,
            int E, int N)
{
    extern __shared__ float sm[];
    float4* sW1f = reinterpret_cast<float4*>(sm + OFF_W1);
    float4* sW2f = reinterpret_cast<float4*>(sm + OFF_W2);
    float4* sW3f = reinterpret_cast<float4*>(sm + OFF_W3);
    float*  sb1  = sm + OFF_B1;
    float*  sb2  = sm + OFF_B2;
    float*  sb3  = sm + OFF_B3;
    float2* slut = reinterpret_cast<float2*>(sm + OFF_LUT);

    const int tid  = threadIdx.x;
    const int lane = tid & 31;
    const int wid  = tid >> 5;
    const int g    = lane >> 2;
    const int j    = lane & 3;

    // ---- preamble: weight fragments (tf32 hi/lo), biases, gelu LUT ----
    for (int idx = tid; idx < 8 * 32; idx += 256) {        // W1
        int nt = idx >> 5, t = idx & 31;
        int kk = t & 3, nn = nt * 8 + (t >> 2);
        float w0 = W1[kk * 64 + nn], w1 = W1[(kk + 4) * 64 + nn];
        u32 h0, l0, h1_, l1; split_tf32(w0, h0, l0); split_tf32(w1, h1_, l1);
        sW1f[idx] = make_float4(__uint_as_float(h0), __uint_as_float(h1_),
                                __uint_as_float(l0), __uint_as_float(l1));
    }
    for (int idx = tid; idx < 32 * 32; idx += 256) {       // W2
        int combo = idx >> 5, t = idx & 31;
        int ks = combo >> 2, nt = combo & 3;
        int kk = ks * 8 + (t & 3), nn = nt * 8 + (t >> 2);
        float w0 = W2[kk * 32 + nn], w1 = W2[(kk + 4) * 32 + nn];
        u32 h0, l0, h1_, l1; split_tf32(w0, h0, l0); split_tf32(w1, h1_, l1);
        sW2f[idx] = make_float4(__uint_as_float(h0), __uint_as_float(h1_),
                                __uint_as_float(l0), __uint_as_float(l1));
    }
    for (int idx = tid; idx < 8 * 32; idx += 256) {        // W3
        int combo = idx >> 5, t = idx & 31;
        int ks = combo >> 1, nt = combo & 1;
        int kk = ks * 8 + (t & 3), nn = nt * 8 + (t >> 2);
        float w0 = W3[kk * 16 + nn], w1 = W3[(kk + 4) * 16 + nn];
        u32 h0, l0, h1_, l1; split_tf32(w0, h0, l0); split_tf32(w1, h1_, l1);
        sW3f[idx] = make_float4(__uint_as_float(h0), __uint_as_float(h1_),
                                __uint_as_float(l0), __uint_as_float(l1));
    }
    if (tid < 64) sb1[tid] = b1[tid];
    if (tid < 32) sb2[tid] = b2[tid];
    if (tid < 16) sb3[tid] = b3[tid];
    for (int i = tid; i < 2048; i += 256) {
        float x0 = (float)(i - 1024) * 0.0078125f;
        float g0 = gelu_exact(x0);
        slut[i] = make_float2(g0, gelu_exact(x0 + 0.0078125f) - g0);
    }
    __syncthreads();

    float* efs = sm + OFF_WARP + wid * WARP_FLOATS;   // [32][8]
    float* h1s = efs + 256;                           // [16][68]
    float* h2s = h1s + 1088;                          // [16][36]
    float* outs = h1s;                                // reuse as [16][20]
    float4* outs4 = reinterpret_cast<float4*>(outs);

    float lsum4[4] = {0, 0, 0, 0}, lsq4[4] = {0, 0, 0, 0};

    const int tiles32 = (E + 31) >> 5;
    const int warpsTotal = gridDim.x * 8;
    const int warpGlobal = blockIdx.x * 8 + wid;

    for (int tb32 = warpGlobal; tb32 < tiles32; tb32 += warpsTotal) {
        const int ebase = tb32 << 5;
        const int e = ebase + lane;
        const bool ev = (e < E);

        int r = ev ? rowi[e] : 0;
        int c = ev ? coli[e] : 0;
        if ((unsigned)r >= (unsigned)N) r = 0;
        if ((unsigned)c >= (unsigned)N) c = 0;

        {   // gather: 2x LDG.128 per endpoint from packed node table
            const float4 ra = *reinterpret_cast<const float4*>(&g_nodepack[8*r]);
            const float4 rb = *reinterpret_cast<const float4*>(&g_nodepack[8*r+4]);
            const float4 ca = *reinterpret_cast<const float4*>(&g_nodepack[8*c]);
            const float4 cb = *reinterpret_cast<const float4*>(&g_nodepack[8*c+4]);

            const float dx = ca.x - ra.x, dy = ca.y - ra.y, dz = ca.z - ra.z;
            const float nrx = ra.w, nry = rb.x, nrz = rb.y;
            const float ncx = ca.w, ncy = cb.x, ncz = cb.y;
            const float ndot = nrx*ncx + nry*ncy + nrz*ncz;
            const float dn = sqrtf(dx*dx + dy*dy + dz*dz) + 1e-8f;
            const float inv = 1.0f / dn;
            float cr = fminf(1.0f, fmaxf(-1.0f, (nrx*dx+nry*dy+nrz*dz)*inv));
            float cc = fminf(1.0f, fmaxf(-1.0f, (ncx*dx+ncy*dy+ncz*dz)*inv));
            float* er = efs + lane * 8;
            er[0] = dx; er[1] = dy; er[2] = dz; er[3] = ndot;
            er[4] = cr; er[5] = cc;
            er[6] = cb.z - rb.z;
            er[7] = cb.w - rb.w;
        }
        __syncwarp();

#pragma unroll
        for (int t = 0; t < 2; t++) {
            const int tb = ebase + t * 16;

            // Layer 1: [16,8] @ [8,64]
            u32 a4[4];
            {
                const float* base = efs + t * 128;
                a4[0] = tf32_of(base[(g    )*8 + j    ]);
                a4[1] = tf32_of(base[(g + 8)*8 + j    ]);
                a4[2] = tf32_of(base[(g    )*8 + j + 4]);
                a4[3] = tf32_of(base[(g + 8)*8 + j + 4]);
            }
            float d1v[8][4];
#pragma unroll
            for (int nt = 0; nt < 8; nt++) {
                d1v[nt][0] = d1v[nt][1] = d1v[nt][2] = d1v[nt][3] = 0.0f;
                float4 bw = sW1f[nt * 32 + lane];
                mma_tf32(d1v[nt][0], d1v[nt][1], d1v[nt][2], d1v[nt][3],
                         a4[0], a4[1], a4[2], a4[3],
                         __float_as_uint(bw.x), __float_as_uint(bw.y));
                mma_tf32(d1v[nt][0], d1v[nt][1], d1v[nt][2], d1v[nt][3],
                         a4[0], a4[1], a4[2], a4[3],
                         __float_as_uint(bw.z), __float_as_uint(bw.w));
            }
#pragma unroll
            for (int nt = 0; nt < 8; nt++) {
                const int cb = nt * 8 + 2 * j;
                const float bx = sb1[cb], by = sb1[cb + 1];
#pragma unroll
                for (int hrow = 0; hrow < 2; hrow++) {
                    float v0 = d1v[nt][2*hrow]     + bx;
                    float v1 = d1v[nt][2*hrow + 1] + by;
                    float t0 = fminf(fmaxf(fmaf(v0, 128.0f, 1024.0f), 0.0f), 2046.999f);
                    float t1 = fminf(fmaxf(fmaf(v1, 128.0f, 1024.0f), 0.0f), 2046.999f);
                    int i0 = (int)t0, i1 = (int)t1;
                    float2 e0 = slut[i0], e1 = slut[i1];
                    float y0 = fmaf(t0 - (float)i0, e0.y, e0.x);
                    float y1 = fmaf(t1 - (float)i1, e1.y, e1.x);
                    if (v0 > 8.0f) y0 = v0;
                    if (v1 > 8.0f) y1 = v1;
                    const int rr = g + 8 * hrow;
                    *reinterpret_cast<float2*>(h1s + rr * H1_PAD + cb) =
                        make_float2(y0, y1);
                }
            }
            __syncwarp();

            // Layer 2: [16,64] @ [64,32]
            float d2v[4][4];
#pragma unroll
            for (int nt = 0; nt < 4; nt++)
                d2v[nt][0] = d2v[nt][1] = d2v[nt][2] = d2v[nt][3] = 0.0f;
#pragma unroll
            for (int ks = 0; ks < 8; ks++) {
                const int cbk = ks * 8;
                a4[0] = tf32_of(h1s[(g    )*H1_PAD + cbk + j    ]);
                a4[1] = tf32_of(h1s[(g + 8)*H1_PAD + cbk + j    ]);
                a4[2] = tf32_of(h1s[(g    )*H1_PAD + cbk + j + 4]);
                a4[3] = tf32_of(h1s[(g + 8)*H1_PAD + cbk + j + 4]);
#pragma unroll
                for (int nt = 0; nt < 4; nt++) {
                    float4 bw = sW2f[(ks * 4 + nt) * 32 + lane];
                    mma_tf32(d2v[nt][0], d2v[nt][1], d2v[nt][2], d2v[nt][3],
                             a4[0], a4[1], a4[2], a4[3],
                             __float_as_uint(bw.x), __float_as_uint(bw.y));
                    mma_tf32(d2v[nt][0], d2v[nt][1], d2v[nt][2], d2v[nt][3],
                             a4[0], a4[1], a4[2], a4[3],
                             __float_as_uint(bw.z), __float_as_uint(bw.w));
                }
            }
#pragma unroll
            for (int nt = 0; nt < 4; nt++) {
                const int cb = nt * 8 + 2 * j;
                const float bx = sb2[cb], by = sb2[cb + 1];
#pragma unroll
                for (int hrow = 0; hrow < 2; hrow++) {
                    float v0 = d2v[nt][2*hrow]     + bx;
                    float v1 = d2v[nt][2*hrow + 1] + by;
                    float t0 = fminf(fmaxf(fmaf(v0, 128.0f, 1024.0f), 0.0f), 2046.999f);
                    float t1 = fminf(fmaxf(fmaf(v1, 128.0f, 1024.0f), 0.0f), 2046.999f);
                    int i0 = (int)t0, i1 = (int)t1;
                    float2 e0 = slut[i0], e1 = slut[i1];
                    float y0 = fmaf(t0 - (float)i0, e0.y, e0.x);
                    float y1 = fmaf(t1 - (float)i1, e1.y, e1.x);
                    if (v0 > 8.0f) y0 = v0;
                    if (v1 > 8.0f) y1 = v1;
                    const int rr = g + 8 * hrow;
                    *reinterpret_cast<float2*>(h2s + rr * H2_PAD + cb) =
                        make_float2(y0, y1);
                }
            }
            __syncwarp();

            // Layer 3: [16,32] @ [32,16]
            float d3v[2][4];
#pragma unroll
            for (int nt = 0; nt < 2; nt++)
                d3v[nt][0] = d3v[nt][1] = d3v[nt][2] = d3v[nt][3] = 0.0f;
#pragma unroll
            for (int ks = 0; ks < 4; ks++) {
                const int cbk = ks * 8;
                a4[0] = tf32_of(h2s[(g    )*H2_PAD + cbk + j    ]);
                a4[1] = tf32_of(h2s[(g + 8)*H2_PAD + cbk + j    ]);
                a4[2] = tf32_of(h2s[(g    )*H2_PAD + cbk + j + 4]);
                a4[3] = tf32_of(h2s[(g + 8)*H2_PAD + cbk + j + 4]);
#pragma unroll
                for (int nt = 0; nt < 2; nt++) {
                    float4 bw = sW3f[(ks * 2 + nt) * 32 + lane];
                    mma_tf32(d3v[nt][0], d3v[nt][1], d3v[nt][2], d3v[nt][3],
                             a4[0], a4[1], a4[2], a4[3],
                             __float_as_uint(bw.x), __float_as_uint(bw.y));
                    mma_tf32(d3v[nt][0], d3v[nt][1], d3v[nt][2], d3v[nt][3],
                             a4[0], a4[1], a4[2], a4[3],
                             __float_as_uint(bw.z), __float_as_uint(bw.w));
                }
            }
            __syncwarp();

            const bool fullTile = (tb + 16 <= E);
#pragma unroll
            for (int nt = 0; nt < 2; nt++) {
                const int cb = nt * 8 + 2 * j;
                const float bx = sb3[cb], by = sb3[cb + 1];
#pragma unroll
                for (int hrow = 0; hrow < 2; hrow++) {
                    float v0 = d3v[nt][2*hrow]     + bx;
                    float v1 = d3v[nt][2*hrow + 1] + by;
                    const int rr = g + 8 * hrow;
                    if (fullTile || (tb + rr < E)) {
                        lsum4[nt*2+0] += v0;
                        lsum4[nt*2+1] += v1;
                        lsq4[nt*2+0]   = fmaf(v0, v0, lsq4[nt*2+0]);
                        lsq4[nt*2+1]   = fmaf(v1, v1, lsq4[nt*2+1]);
                    }
                    *reinterpret_cast<float2*>(outs + rr * OUT_PAD + cb) =
                        make_float2(v0, v1);
                }
            }
            __syncwarp();

            {   // scatter: lanes 0-15 -> row endpoint, 16-31 -> col endpoint
                const int le = lane & 15;
                const int src = t * 16 + le;
                const int rr = __shfl_sync(0xffffffffu, r, src);
                const int cc = __shfl_sync(0xffffffffu, c, src);
                if (tb + le < E) {
                    const int node = (lane < 16) ? rr : cc;
                    float4* dst = reinterpret_cast<float4*>(
                        &g_node_acc[(size_t)node * 16]);
#pragma unroll
                    for (int q = 0; q < 4; q++)
                        atomicAdd(dst + q, outs4[le * 5 + q]);
                    atomicAdd(&g_degree[node], 1.0f);
                }
            }
            __syncwarp();
        }
    }

    // ---- BN-stat reduction ----
#pragma unroll
    for (int i = 0; i < 4; i++) {
#pragma unroll
        for (int o = 4; o < 32; o <<= 1) {
            lsum4[i] += __shfl_xor_sync(0xffffffffu, lsum4[i], o);
            lsq4[i]  += __shfl_xor_sync(0xffffffffu, lsq4[i],  o);
        }
    }
    if (lane < 4) {
#pragma unroll
        for (int i = 0; i < 4; i++) {
            const int col = (i >> 1) * 8 + 2 * lane + (i & 1);
            atomicAdd(&g_esum[col], (double)lsum4[i]);
            atomicAdd(&g_esq[col],  (double)lsq4[i]);
        }
    }
}

// ---------------------------------------------------------------------------
__global__ void k_ecoef(const float* __restrict__ g, const float* __restrict__ b,
                        int E)
{
    int j = threadIdx.x;
    if (j < 16) {
        double invE = 1.0 / (double)E;
        double m = g_esum[j] * invE;
        double v = g_esq[j] * invE - m * m;
        double s = (double)g[j] / sqrt(v + 1e-5);
        g_es[j] = (float)s;
        g_et[j] = (float)((double)b[j] - m * s);
    }
}

// ---------------------------------------------------------------------------
__global__ __launch_bounds__(256)
void k_node(const float* __restrict__ Wp, const float* __restrict__ bp,
            int N, float* __restrict__ out)
{
    __shared__ float sWp[256], sbp[16], ses[16], set_[16];
    __shared__ float redS[8][16], redQ[8][16];
    if (threadIdx.x < 256) sWp[threadIdx.x] = Wp[threadIdx.x];
    if (threadIdx.x < 16) {
        sbp[threadIdx.x]  = bp[threadIdx.x];
        ses[threadIdx.x]  = g_es[threadIdx.x];
        set_[threadIdx.x] = g_et[threadIdx.x];
    }
    __syncthreads();

    float lsum[16], lsq[16];
#pragma unroll
    for (int k = 0; k < 16; k++) { lsum[k] = 0.0f; lsq[k] = 0.0f; }

    const int n = blockIdx.x * blockDim.x + threadIdx.x;
    if (n < N) {
        const float deg  = g_degree[n];
        const float invd = 1.0f / fmaxf(deg, 1.0f);
        float pre[16];
#pragma unroll
        for (int j = 0; j < 16; j++) {
            const float a = g_node_acc[n * 16 + j];
            pre[j] = (ses[j] * a + set_[j] * deg) * invd;
        }
        float y[16];
#pragma unroll
        for (int k = 0; k < 16; k++) y[k] = sbp[k];
#pragma unroll
        for (int j = 0; j < 16; j++)
#pragma unroll
            for (int k = 0; k < 16; k++) y[k] = fmaf(pre[j], sWp[j*16 + k], y[k]);
#pragma unroll
        for (int k = 0; k < 16; k++) {
            out[n * 16 + k] = y[k];
            lsum[k] = y[k];
            lsq[k]  = y[k] * y[k];
        }
    }

#pragma unroll
    for (int k = 0; k < 16; k++) {
        float s = lsum[k], q = lsq[k];
#pragma unroll
        for (int o = 16; o > 0; o >>= 1) {
            s += __shfl_xor_sync(0xffffffffu, s, o);
            q += __shfl_xor_sync(0xffffffffu, q, o);
        }
        if ((threadIdx.x & 31) == 0) {
            redS[threadIdx.x >> 5][k] = s;
            redQ[threadIdx.x >> 5][k] = q;
        }
    }
    __syncthreads();
    if (threadIdx.x < 16) {
        double s = 0.0, q = 0.0;
#pragma unroll
        for (int w = 0; w < 8; w++) { s += (double)redS[w][threadIdx.x];
                                      q += (double)redQ[w][threadIdx.x]; }
        atomicAdd(&g_nsum[threadIdx.x], s);
        atomicAdd(&g_nsq[threadIdx.x],  q);
    }
}

// ---------------------------------------------------------------------------
__global__ void k_ncoef(const float* __restrict__ g, const float* __restrict__ b,
                        int N)
{
    int j = threadIdx.x;
    if (j < 16) {
        double invN = 1.0 / (double)N;
        double m = g_nsum[j] * invN;
        double v = g_nsq[j] * invN - m * m;
        double s = (double)g[j] / sqrt(v + 1e-5);
        g_ns[j] = (float)s;
        g_nt[j] = (float)((double)b[j] - m * s);
    }
}

// ---------------------------------------------------------------------------
__global__ void k_norm(float* __restrict__ out, int total)
{
    int i = blockIdx.x * blockDim.x + threadIdx.x;
    if (i < total) {
        int j = i & 15;
        out[i] = fmaf(out[i], g_ns[j], g_nt[j]);
    }
}

// ---------------------------------------------------------------------------
extern "C" void kernel_launch(void* const* d_in, const int* in_sizes, int n_in,
                              void* d_out, int out_size)
{
    const float* coords  = (const float*)d_in[0];
    const float* normals = (const float*)d_in[1];
    const float* curv    = (const float*)d_in[2];
    const int*   ei      = (const int*)d_in[3];
    const float* W1 = (const float*)d_in[4];
    const float* b1 = (const float*)d_in[5];
    const float* W2 = (const float*)d_in[6];
    const float* b2 = (const float*)d_in[7];
    const float* W3 = (const float*)d_in[8];
    const float* b3 = (const float*)d_in[9];
    const float* Wp = (const float*)d_in[10];
    const float* bp = (const float*)d_in[11];
    const float* beg = (const float*)d_in[12];
    const float* beb = (const float*)d_in[13];
    const float* bng = (const float*)d_in[14];
    const float* bnb = (const float*)d_in[15];

    const int N = in_sizes[0] / 3;
    const int E = in_sizes[3] / 2;
    const int* row = ei;
    const int* col = ei + E;
    float* out = (float*)d_out;

    const int smemBytes = (OFF_WARP + 8 * WARP_FLOATS) * 4;
    static bool attrSet = false;
    if (!attrSet) {
        cudaFuncSetAttribute(k_edge, cudaFuncAttributeMaxDynamicSharedMemorySize,
                             smemBytes);
        attrSet = true;
    }

    k_zero<<<(N * 16 + 255) / 256, 256>>>(N);
    k_pack<<<(N + 255) / 256, 256>>>(coords, normals, curv, N);
    k_edge<<<296, 256, smemBytes>>>(row, col, W1, b1, W2, b2, W3, b3, E, N);
    k_ecoef<<<1, 32>>>(beg, beb, E);
    k_node<<<(N + 255) / 256, 256>>>(Wp, bp, N, out);
    k_ncoef<<<1, 32>>>(bng, bnb, N);
    k_norm<<<(N * 16 + 255) / 256, 256>>>(out, N * 16);
}